// round 15
// baseline (speedup 1.0000x reference)
#include <cuda_runtime.h>
#include <cstdint>

// ============================================================================
// AddNoise: out[b,j] = (sigma_j + 0.1*normal(k4)[b,j]) * x[b,j]
//                      + (mu_j + uniform(k3, -0.05, 0.05)[b,j])
// Threefry2x32 partitionable bits, keys k1..k4 = split(key(42), 4) foldlike.
//
// R15 = R14 (best, 175.3us) + stride-2 grid loop with hoisted column params:
//   grid halved to 16384 CTAs; element stride between iterations = 2^24,
//   a multiple of NCOLS -> column index identical across iterations, so the
//   g_cols loads + unpack hoist out of the loop (amortize prologue over 8
//   elems). #pragma unroll 1 keeps register pressure at the R14 level
//   (R8 lesson: 8 CONCURRENT elems -> 59 regs -> regression).
// Pinned lessons: no IMAD.WIDE (R2), no mul-split rotates (R4), no IADD3
// injection folds (R5), no IMAD.HI (R6), keep erfinvf (R5/R10), 4 concurrent
// elem/thread at ~70% occ (R7/R8/R9), 256-thread blocks (R13).
// ============================================================================

#define NCOLS 8192
#define NROWS 4096
#define NELEM (NCOLS * NROWS)   // 2^25
#define NITER 2                 // grid-stride iterations per thread

struct KeyPair { unsigned a, b; };

constexpr unsigned rotl_c(unsigned x, int d) { return (x << d) | (x >> (32 - d)); }

constexpr KeyPair tf_pair_c(unsigned k0, unsigned k1, unsigned x0, unsigned x1) {
    unsigned ks0 = k0, ks1 = k1, ks2 = k0 ^ k1 ^ 0x1BD11BDAu;
    x0 += ks0; x1 += ks1;
    const int rotA[4] = {13, 15, 26, 6};
    const int rotB[4] = {17, 29, 16, 24};
    unsigned ks[3] = {ks0, ks1, ks2};
    for (int i = 0; i < 5; ++i) {
        const int* rot = (i & 1) ? rotB : rotA;
        for (int r = 0; r < 4; ++r) {
            x0 += x1;
            x1 = rotl_c(x1, rot[r]);
            x1 ^= x0;
        }
        x0 += ks[(i + 1) % 3];
        x1 += ks[(i + 2) % 3] + (unsigned)(i + 1);
    }
    return {x0, x1};
}

constexpr KeyPair K1 = tf_pair_c(0u, 42u, 0u, 0u);
constexpr KeyPair K2 = tf_pair_c(0u, 42u, 0u, 1u);
constexpr KeyPair K3 = tf_pair_c(0u, 42u, 0u, 2u);
constexpr KeyPair K4 = tf_pair_c(0u, 42u, 0u, 3u);

// integer add as IMAD (fma pipe): a * one + b, one == 1 at runtime
#define ADDU(a, b) ((a) * one + (b))
// One threefry round: IMAD (fma) + SHF (alu) + LOP3 (alu).
#define TFR(r) { x0 = ADDU(x1, x0); x1 = __funnelshift_l(x1, x1, (r)) ^ x0; }

// threefry2x32(key, (0, e0 + i)) -> o0 ^ o1 (partitionable 32-bit bits).
template <unsigned KA, unsigned KB>
__device__ __forceinline__ unsigned tf_xor(unsigned e0, unsigned i, unsigned one) {
    constexpr unsigned KC = KA ^ KB ^ 0x1BD11BDAu;
    unsigned x0 = KA;
    unsigned x1 = ADDU(e0, KB + i);       // single IMAD, immediate addend
    TFR(13) TFR(15) TFR(26) TFR(6)
    x0 = ADDU(x0, KB);  x1 = ADDU(x1, KC + 1u);
    TFR(17) TFR(29) TFR(16) TFR(24)
    x0 = ADDU(x0, KC);  x1 = ADDU(x1, KA + 2u);
    TFR(13) TFR(15) TFR(26) TFR(6)
    x0 = ADDU(x0, KA);  x1 = ADDU(x1, KB + 3u);
    TFR(17) TFR(29) TFR(16) TFR(24)
    x0 = ADDU(x0, KB);  x1 = ADDU(x1, KC + 4u);
    TFR(13) TFR(15) TFR(26) TFR(6)
    x0 = ADDU(x0, KC);  x1 = ADDU(x1, KA + 5u);
    return x0 ^ x1;
}

// denormal mantissa payload: k * 2^-149, k = bits>>9  (single SHF, alu)
__device__ __forceinline__ float fden(unsigned bits) {
    return __uint_as_float(bits >> 9);
}

// classic path for the tiny column kernel
__device__ __forceinline__ float u01s(unsigned bits) {
    return __uint_as_float((bits >> 9) | 0x3f800000u) - 1.0f;
}

// Per-column parameters: (mu_j - 0.05_exact_in_double, sigma_j)
__device__ float2 g_cols[NCOLS];

__global__ void col_kernel(unsigned one) {
    unsigned j = blockIdx.x * blockDim.x + threadIdx.x;  // 8192 threads exactly
    float fmu = u01s(tf_xor<K1.a, K1.b>(j, 0u, one));
    float mu  = fmaf(fmu, 0.2f, -0.1f);            // >= -0.1 always; fmax no-op
    float fsg = u01s(tf_xor<K2.a, K2.b>(j, 0u, one));
    float sg  = fmaf(fsg, 1.0f, 1.0f);             // >= 1.0 always
    // table holds mu - 0.05 (exact in double): m = fma(k*2^-149, 0.1*2^126, .)
    double d  = (double)mu - (double)0.05f;
    g_cols[j] = make_float2((float)d, sg);
}

// grid: NELEM/4/NITER threads total; per-iteration element stride = 2^24,
// a multiple of NCOLS -> column params constant across iterations.
__global__ void __launch_bounds__(256, 4)
noise_kernel(const float4* __restrict__ x, float4* __restrict__ out,
             unsigned one, unsigned two, unsigned four) {
    unsigned t0     = blockIdx.x * blockDim.x + threadIdx.x;
    unsigned nthr   = (NELEM / 4) / NITER;          // compile-time constant
    unsigned cidx   = (t0 * two) & ((NCOLS / 2) - 1); // float4-table idx = j0/2

    const float4* cp = reinterpret_cast<const float4*>(g_cols);
    float4 c01 = cp[cidx + 0];            // {muC0, sg0, muC1, sg1}
    float4 c23 = cp[cidx + 1];            // {muC2, sg2, muC3, sg3}

    float muC[4] = {c01.x, c01.z, c23.x, c23.z};
    float sg[4]  = {c01.y, c01.w, c23.y, c23.w};

    constexpr float LO     = -0.99999994039535522461f;  // nextafterf(-1, 0)
    constexpr float SC     = 0.1f * 1.41421356237309515f;
    constexpr float TWO126 = 8.507059173023462e37f;     // 2^126
    constexpr float TWO127 = 1.7014118346046923e38f;    // 2^127
    constexpr float C1     = 0.1f * TWO126;             // exact (exp shift)

#pragma unroll 1
    for (unsigned it = 0; it < NITER; ++it) {
        unsigned t  = t0 + it * nthr;
        unsigned e0 = t * four;           // IMAD (fma)

        float4 xv = x[t];
        float xs[4]  = {xv.x, xv.y, xv.z, xv.w};
        float res[4];

#pragma unroll
        for (int i = 0; i < 4; ++i) {
            // mMat: m = fma(k3den, 0.1*2^126, mu-0.05)
            float f3 = fden(tf_xor<K3.a, K3.b>(e0, (unsigned)i, one));
            float m  = fmaf(f3, C1, muC[i]);

            // sMat: u = fma(k4den, 2^127, LO) -- bit-identical to (f4raw-1)*2+LO
            float f4 = fden(tf_xor<K4.a, K4.b>(e0, (unsigned)i, one));
            float u  = fmaf(f4, TWO127, LO);      // >= LO always
            float s  = fmaf(erfinvf(u), SC, sg[i]);

            res[i] = fmaf(s, xs[i], m);
        }

        out[t] = make_float4(res[0], res[1], res[2], res[3]);
    }
}

extern "C" void kernel_launch(void* const* d_in, const int* in_sizes, int n_in,
                              void* d_out, int out_size) {
    const float* x = (const float*)d_in[0];
    float* out = (float*)d_out;

    col_kernel<<<NCOLS / 256, 256>>>(1u);
    noise_kernel<<<((NELEM / 4) / NITER) / 256, 256>>>(
        reinterpret_cast<const float4*>(x), reinterpret_cast<float4*>(out),
        1u, 2u, 4u);
}

// round 16
// speedup vs baseline: 1.0218x; 1.0218x over previous
#include <cuda_runtime.h>
#include <cstdint>

// ============================================================================
// AddNoise: out[b,j] = (sigma_j + 0.1*normal(k4)[b,j]) * x[b,j]
//                      + (mu_j + uniform(k3, -0.05, 0.05)[b,j])
// Threefry2x32 partitionable bits, keys k1..k4 = split(key(42), 4) foldlike.
//
// R16 = R14 verbatim (session champion, 175.3us) -- stability re-bench.
// Converged configuration:
//   - 4 elements/thread, 256-thread blocks, launch_bounds(256,4) (~70% occ,
//     the measured optimum of the occupancy/ILP surface)
//   - all integer adds as IMAD via opaque `one` arg (fma pipe)
//   - counter offset folded into x1-init immediate
//   - denormal-FFMA bit->float folds (u path bit-identical; m path folds
//     0.1 scale + mu-0.05 into one FFMA with denormal multiplicand)
//   - cidx = (t*two)&(NCOLS/2-1) directly (one fewer SHF)
//   - CUDA erfinvf (beats Giles polynomial on this chip)
// Pinned regression lessons: no IMAD.WIDE (R2), no mul-split rotates (R4),
// no IADD3 injection folds (R5), no IMAD.HI (R6), no Giles erfinv (R10),
// no 8 concurrent elems (R8), no 512-thread blocks (R13), no grid-stride
// loops (R15).
// alu core = 2 ops x 40 threefry rounds/elem, structural for bit-exact JAX
// reproduction; kernel runs at ~90% of that pipe roofline.
// ============================================================================

#define NCOLS 8192
#define NROWS 4096
#define NELEM (NCOLS * NROWS)   // 2^25

struct KeyPair { unsigned a, b; };

constexpr unsigned rotl_c(unsigned x, int d) { return (x << d) | (x >> (32 - d)); }

constexpr KeyPair tf_pair_c(unsigned k0, unsigned k1, unsigned x0, unsigned x1) {
    unsigned ks0 = k0, ks1 = k1, ks2 = k0 ^ k1 ^ 0x1BD11BDAu;
    x0 += ks0; x1 += ks1;
    const int rotA[4] = {13, 15, 26, 6};
    const int rotB[4] = {17, 29, 16, 24};
    unsigned ks[3] = {ks0, ks1, ks2};
    for (int i = 0; i < 5; ++i) {
        const int* rot = (i & 1) ? rotB : rotA;
        for (int r = 0; r < 4; ++r) {
            x0 += x1;
            x1 = rotl_c(x1, rot[r]);
            x1 ^= x0;
        }
        x0 += ks[(i + 1) % 3];
        x1 += ks[(i + 2) % 3] + (unsigned)(i + 1);
    }
    return {x0, x1};
}

constexpr KeyPair K1 = tf_pair_c(0u, 42u, 0u, 0u);
constexpr KeyPair K2 = tf_pair_c(0u, 42u, 0u, 1u);
constexpr KeyPair K3 = tf_pair_c(0u, 42u, 0u, 2u);
constexpr KeyPair K4 = tf_pair_c(0u, 42u, 0u, 3u);

// integer add as IMAD (fma pipe): a * one + b, one == 1 at runtime
#define ADDU(a, b) ((a) * one + (b))
// One threefry round: IMAD (fma) + SHF (alu) + LOP3 (alu).
#define TFR(r) { x0 = ADDU(x1, x0); x1 = __funnelshift_l(x1, x1, (r)) ^ x0; }

// threefry2x32(key, (0, e0 + i)) -> o0 ^ o1 (partitionable 32-bit bits).
template <unsigned KA, unsigned KB>
__device__ __forceinline__ unsigned tf_xor(unsigned e0, unsigned i, unsigned one) {
    constexpr unsigned KC = KA ^ KB ^ 0x1BD11BDAu;
    unsigned x0 = KA;
    unsigned x1 = ADDU(e0, KB + i);       // single IMAD, immediate addend
    TFR(13) TFR(15) TFR(26) TFR(6)
    x0 = ADDU(x0, KB);  x1 = ADDU(x1, KC + 1u);
    TFR(17) TFR(29) TFR(16) TFR(24)
    x0 = ADDU(x0, KC);  x1 = ADDU(x1, KA + 2u);
    TFR(13) TFR(15) TFR(26) TFR(6)
    x0 = ADDU(x0, KA);  x1 = ADDU(x1, KB + 3u);
    TFR(17) TFR(29) TFR(16) TFR(24)
    x0 = ADDU(x0, KB);  x1 = ADDU(x1, KC + 4u);
    TFR(13) TFR(15) TFR(26) TFR(6)
    x0 = ADDU(x0, KC);  x1 = ADDU(x1, KA + 5u);
    return x0 ^ x1;
}

// denormal mantissa payload: k * 2^-149, k = bits>>9  (single SHF, alu)
__device__ __forceinline__ float fden(unsigned bits) {
    return __uint_as_float(bits >> 9);
}

// classic path for the tiny column kernel
__device__ __forceinline__ float u01s(unsigned bits) {
    return __uint_as_float((bits >> 9) | 0x3f800000u) - 1.0f;
}

// Per-column parameters: (mu_j - 0.05_exact_in_double, sigma_j)
__device__ float2 g_cols[NCOLS];

__global__ void col_kernel(unsigned one) {
    unsigned j = blockIdx.x * blockDim.x + threadIdx.x;  // 8192 threads exactly
    float fmu = u01s(tf_xor<K1.a, K1.b>(j, 0u, one));
    float mu  = fmaf(fmu, 0.2f, -0.1f);            // >= -0.1 always; fmax no-op
    float fsg = u01s(tf_xor<K2.a, K2.b>(j, 0u, one));
    float sg  = fmaf(fsg, 1.0f, 1.0f);             // >= 1.0 always
    // table holds mu - 0.05 (exact in double): m = fma(k*2^-149, 0.1*2^126, .)
    double d  = (double)mu - (double)0.05f;
    g_cols[j] = make_float2((float)d, sg);
}

__global__ void __launch_bounds__(256, 4)
noise_kernel(const float4* __restrict__ x, float4* __restrict__ out,
             unsigned one, unsigned two, unsigned four) {
    unsigned t    = blockIdx.x * blockDim.x + threadIdx.x;
    unsigned e0   = t * four;                       // IMAD (fma)
    unsigned cidx = (t * two) & ((NCOLS / 2) - 1);  // float4-table index = j0/2

    float4 xv = x[t];

    const float4* cp = reinterpret_cast<const float4*>(g_cols);
    float4 c01 = cp[cidx + 0];            // {muC0, sg0, muC1, sg1}
    float4 c23 = cp[cidx + 1];            // {muC2, sg2, muC3, sg3}

    float muC[4] = {c01.x, c01.z, c23.x, c23.z};
    float sg[4]  = {c01.y, c01.w, c23.y, c23.w};
    float xs[4]  = {xv.x, xv.y, xv.z, xv.w};
    float res[4];

    constexpr float LO     = -0.99999994039535522461f;  // nextafterf(-1, 0)
    constexpr float SC     = 0.1f * 1.41421356237309515f;
    constexpr float TWO126 = 8.507059173023462e37f;     // 2^126
    constexpr float TWO127 = 1.7014118346046923e38f;    // 2^127
    constexpr float C1     = 0.1f * TWO126;             // exact (exp shift)

#pragma unroll
    for (int i = 0; i < 4; ++i) {
        // mMat: m = mu + uniform(k3,-0.05,0.05) = fma(k3den, 0.1*2^126, mu-0.05)
        float f3 = fden(tf_xor<K3.a, K3.b>(e0, (unsigned)i, one));
        float m  = fmaf(f3, C1, muC[i]);

        // sMat: u = fma(k4den, 2^127, LO) -- bit-identical to (f4raw-1)*2+LO
        float f4 = fden(tf_xor<K4.a, K4.b>(e0, (unsigned)i, one));
        float u  = fmaf(f4, TWO127, LO);      // >= LO always
        float s  = fmaf(erfinvf(u), SC, sg[i]);

        res[i] = fmaf(s, xs[i], m);
    }

    out[t] = make_float4(res[0], res[1], res[2], res[3]);
}

extern "C" void kernel_launch(void* const* d_in, const int* in_sizes, int n_in,
                              void* d_out, int out_size) {
    const float* x = (const float*)d_in[0];
    float* out = (float*)d_out;

    col_kernel<<<NCOLS / 256, 256>>>(1u);
    noise_kernel<<<(NELEM / 4) / 256, 256>>>(
        reinterpret_cast<const float4*>(x), reinterpret_cast<float4*>(out),
        1u, 2u, 4u);
}